// round 4
// baseline (speedup 1.0000x reference)
#include <cuda_runtime.h>
#include <cuda_bf16.h>

// ---------------------------------------------------------------------------
// AdditiveAttention: B=4, LQ=LK=256, D=768
//   q = query@Wq + bq ; k = key@Wk + bk ; v = value@Wv + bv
//   scores[b,q,k] = sum_d Ws[d] * tanh(q[b,q,d] + k[b,k,d])   (+bs cancels in softmax)
//   weights = softmax_k(scores) ; attended = weights @ v
// Outputs: attended [4,256,768] then weights [4,256,256] (flattened, fp32)
// ---------------------------------------------------------------------------

#define B_ 4
#define L_ 256
#define D_ 768
#define M_ (B_ * L_)          // 1024 rows for projection GEMMs

// scratch (allocation-free rule: __device__ globals)
__device__ __align__(16) float g_qp[M_ * D_];
__device__ __align__(16) float g_kp[M_ * D_];
__device__ __align__(16) float g_vp[M_ * D_];

// ---------------------------------------------------------------------------
// Kernel 1: projection GEMM  Y[m,n] = sum_k X[m,k]*W[k,n] + bias[n]
// 64x128 tile, BK=8, 256 threads, 4x8 micro-tile, double-buffered smem.
// grid = (6, 16, 3) = 288 CTAs -> 2 CTAs/SM (fixes round-3's occ=12.4%).
// ---------------------------------------------------------------------------
__global__ __launch_bounds__(256, 2)
void proj_gemm_kernel(const float* __restrict__ Xq, const float* __restrict__ Xk,
                      const float* __restrict__ Xv,
                      const float* __restrict__ Wq, const float* __restrict__ bq,
                      const float* __restrict__ Wk, const float* __restrict__ bk,
                      const float* __restrict__ Wv, const float* __restrict__ bv)
{
    const int z = blockIdx.z;
    const float* X    = (z == 0) ? Xq : (z == 1) ? Xk : Xv;
    const float* W    = (z == 0) ? Wq : (z == 1) ? Wk : Wv;
    const float* bias = (z == 0) ? bq : (z == 1) ? bk : bv;
    float*       Y    = (z == 0) ? g_qp : (z == 1) ? g_kp : g_vp;

    __shared__ __align__(16) float As[2][8][64];    // [buf][k][m]  4 KB
    __shared__ __align__(16) float Bs[2][8][128];   // [buf][k][n]  8 KB

    const int tid = threadIdx.x;
    const int m0 = blockIdx.y * 64;
    const int n0 = blockIdx.x * 128;

    // A loader (threads 0..127): row = tid/2, col4 = (tid&1)*4
    const int a_row = tid >> 1;            // 0..63 when tid<128
    const int a_col = (tid & 1) * 4;
    const bool a_ld = (tid < 128);
    // B loader (all 256): krow = tid/32, col4 = (tid&31)*4
    const int b_row = tid >> 5;
    const int b_col = (tid & 31) * 4;

    const float* Abase = X + (size_t)(m0 + a_row) * D_ + a_col;
    const float* Bbase = W + (size_t)b_row * D_ + n0 + b_col;

    const int NCHUNK = D_ / 8;   // 96

    float4 af = a_ld ? *(const float4*)(Abase) : make_float4(0.f, 0.f, 0.f, 0.f);
    float4 bf = *(const float4*)(Bbase);

    int buf = 0;
    if (a_ld) {
        As[buf][a_col + 0][a_row] = af.x;
        As[buf][a_col + 1][a_row] = af.y;
        As[buf][a_col + 2][a_row] = af.z;
        As[buf][a_col + 3][a_row] = af.w;
    }
    *(float4*)&Bs[buf][b_row][b_col] = bf;
    __syncthreads();

    const int tx = tid & 15;    // n: 8 cols each
    const int ty = tid >> 4;    // m: 4 rows each

    float acc[4][8];
    #pragma unroll
    for (int i = 0; i < 4; i++)
        #pragma unroll
        for (int j = 0; j < 8; j++) acc[i][j] = 0.f;

    for (int kt = 0; kt < NCHUNK; kt++) {
        float4 af_n, bf_n;
        if (kt + 1 < NCHUNK) {
            if (a_ld) af_n = *(const float4*)(Abase + (kt + 1) * 8);
            bf_n = *(const float4*)(Bbase + (size_t)(kt + 1) * 8 * D_);
        }
        #pragma unroll
        for (int kk = 0; kk < 8; kk++) {
            float a_frag[4], b_frag[8];
            *(float4*)&a_frag[0] = *(const float4*)&As[buf][kk][ty * 4];
            *(float4*)&b_frag[0] = *(const float4*)&Bs[buf][kk][tx * 8];
            *(float4*)&b_frag[4] = *(const float4*)&Bs[buf][kk][tx * 8 + 4];
            #pragma unroll
            for (int i = 0; i < 4; i++)
                #pragma unroll
                for (int j = 0; j < 8; j++)
                    acc[i][j] += a_frag[i] * b_frag[j];
        }
        if (kt + 1 < NCHUNK) {
            buf ^= 1;
            if (a_ld) {
                As[buf][a_col + 0][a_row] = af_n.x;
                As[buf][a_col + 1][a_row] = af_n.y;
                As[buf][a_col + 2][a_row] = af_n.z;
                As[buf][a_col + 3][a_row] = af_n.w;
            }
            *(float4*)&Bs[buf][b_row][b_col] = bf_n;
            __syncthreads();
        }
    }

    // epilogue: + bias, store
    float bv8[8];
    #pragma unroll
    for (int j = 0; j < 8; j++) bv8[j] = __ldg(bias + n0 + tx * 8 + j);

    #pragma unroll
    for (int i = 0; i < 4; i++) {
        float* yrow = Y + (size_t)(m0 + ty * 4 + i) * D_ + n0 + tx * 8;
        float4 o0, o1;
        o0.x = acc[i][0] + bv8[0]; o0.y = acc[i][1] + bv8[1];
        o0.z = acc[i][2] + bv8[2]; o0.w = acc[i][3] + bv8[3];
        o1.x = acc[i][4] + bv8[4]; o1.y = acc[i][5] + bv8[5];
        o1.z = acc[i][6] + bv8[6]; o1.w = acc[i][7] + bv8[7];
        *(float4*)(yrow)     = o0;
        *(float4*)(yrow + 4) = o1;
    }
}

// ---------------------------------------------------------------------------
// Kernel 2: fused scores (MUFU.TANH) + softmax + attended  (round-2 structure,
// inner loop rewritten with float4 LDS: 10 LDS.128 / 32-tanh chunk vs 40 scalar)
// TQ=4: grid = 256 CTAs of 256 threads, 2 CTAs/SM.
// ---------------------------------------------------------------------------
#define TQ 4

__device__ __forceinline__ float tanh_fast(float x) {
    float y;
    asm("tanh.approx.f32 %0, %1;" : "=f"(y) : "f"(x));
    return y;
}

__global__ __launch_bounds__(256, 2)
void attn_kernel(const float* __restrict__ Ws,
                 float* __restrict__ out_att,   // may be null
                 float* __restrict__ out_w)     // may be null
{
    __shared__ __align__(16) float sq[TQ][D_];     // 12 KB  q tile
    __shared__ __align__(16) float sws[D_];        //  3 KB  Ws
    __shared__ float ssc[TQ][L_];                  //  4 KB  scores -> weights
    __shared__ float smax[TQ], sinv[TQ];

    const int tid = threadIdx.x;
    const int b  = blockIdx.x >> 6;                // 64 q-tiles per batch
    const int q0 = (blockIdx.x & 63) * TQ;

    // load q tile (contiguous rows) + Ws
    const float4* qbase = (const float4*)(g_qp + (size_t)(b * L_ + q0) * D_);
    #pragma unroll
    for (int i = tid; i < TQ * D_ / 4; i += 256)
        ((float4*)&sq[0][0])[i] = qbase[i];
    for (int i = tid; i < D_ / 4; i += 256)
        ((float4*)sws)[i] = ((const float4*)Ws)[i];
    __syncthreads();

    // ---- scores: acc[q] = sum_d Ws[d]*tanh(q[q][d] + k[t][d]) ----
    const float4* kb4 = (const float4*)(g_kp + ((size_t)b * L_ + tid) * D_);
    float acc[TQ];
    #pragma unroll
    for (int q = 0; q < TQ; q++) acc[q] = 0.f;

    float4 c0 = kb4[0], c1 = kb4[1];   // current 8 k-values in regs
    #pragma unroll 1
    for (int ch = 0; ch < D_ / 8; ch++) {
        float4 p0, p1;
        if (ch + 1 < D_ / 8) {          // prefetch next k chunk (hides L2 lat)
            p0 = kb4[(ch + 1) * 2];
            p1 = kb4[(ch + 1) * 2 + 1];
        }
        const float4 w0 = *(const float4*)&sws[ch * 8];
        const float4 w1 = *(const float4*)&sws[ch * 8 + 4];
        #pragma unroll
        for (int q = 0; q < TQ; q++) {
            const float4 a0 = *(const float4*)&sq[q][ch * 8];
            const float4 a1 = *(const float4*)&sq[q][ch * 8 + 4];
            float s;
            s  = w0.x * tanh_fast(a0.x + c0.x);
            s += w0.y * tanh_fast(a0.y + c0.y);
            s += w0.z * tanh_fast(a0.z + c0.z);
            s += w0.w * tanh_fast(a0.w + c0.w);
            s += w1.x * tanh_fast(a1.x + c1.x);
            s += w1.y * tanh_fast(a1.y + c1.y);
            s += w1.z * tanh_fast(a1.z + c1.z);
            s += w1.w * tanh_fast(a1.w + c1.w);
            acc[q] += s;
        }
        c0 = p0; c1 = p1;
    }

    #pragma unroll
    for (int q = 0; q < TQ; q++) ssc[q][tid] = acc[q];
    __syncthreads();

    // ---- softmax over k (warp w reduces row w) ----
    const int w = tid >> 5, lane = tid & 31;
    if (w < TQ) {
        float m = -1e30f;
        #pragma unroll
        for (int j = 0; j < 8; j++) m = fmaxf(m, ssc[w][lane + j * 32]);
        #pragma unroll
        for (int o = 16; o > 0; o >>= 1) m = fmaxf(m, __shfl_xor_sync(0xffffffffu, m, o));
        float s = 0.f;
        #pragma unroll
        for (int j = 0; j < 8; j++) s += __expf(ssc[w][lane + j * 32] - m);
        #pragma unroll
        for (int o = 16; o > 0; o >>= 1) s += __shfl_xor_sync(0xffffffffu, s, o);
        if (lane == 0) { smax[w] = m; sinv[w] = 1.0f / s; }
    }
    __syncthreads();

    float wt[TQ];
    #pragma unroll
    for (int q = 0; q < TQ; q++)
        wt[q] = __expf(acc[q] - smax[q]) * sinv[q];

    #pragma unroll
    for (int q = 0; q < TQ; q++) ssc[q][tid] = wt[q];
    if (out_w) {
        #pragma unroll
        for (int q = 0; q < TQ; q++)
            out_w[((size_t)(b * L_ + q0 + q)) * L_ + tid] = wt[q];
    }
    __syncthreads();

    // ---- attended: out[b,q,:] = sum_k w[q][k] * v[b,k,:]  (cols t, t+256, t+512)
    if (out_att) {
        float a0[TQ], a1[TQ], a2[TQ];
        #pragma unroll
        for (int q = 0; q < TQ; q++) { a0[q] = 0.f; a1[q] = 0.f; a2[q] = 0.f; }
        const float* vb = g_vp + (size_t)b * L_ * D_;
        #pragma unroll 4
        for (int kk = 0; kk < L_; kk++) {
            const float* vr = vb + (size_t)kk * D_;
            const float v0 = vr[tid];
            const float v1 = vr[tid + 256];
            const float v2 = vr[tid + 512];
            #pragma unroll
            for (int q = 0; q < TQ; q++) {
                const float ww = ssc[q][kk];
                a0[q] += ww * v0;
                a1[q] += ww * v1;
                a2[q] += ww * v2;
            }
        }
        #pragma unroll
        for (int q = 0; q < TQ; q++) {
            float* o = out_att + ((size_t)(b * L_ + q0 + q)) * D_;
            o[tid]       = a0[q];
            o[tid + 256] = a1[q];
            o[tid + 512] = a2[q];
        }
    }
}

// ---------------------------------------------------------------------------
extern "C" void kernel_launch(void* const* d_in, const int* in_sizes, int n_in,
                              void* d_out, int out_size)
{
    const float* query = (const float*)d_in[0];
    const float* key   = (const float*)d_in[1];
    const float* value = (const float*)d_in[2];
    const float* Wq    = (const float*)d_in[3];
    const float* bq    = (const float*)d_in[4];
    const float* Wk    = (const float*)d_in[5];
    const float* bk    = (const float*)d_in[6];
    const float* Wv    = (const float*)d_in[7];
    const float* bv    = (const float*)d_in[8];
    const float* Ws    = (const float*)d_in[9];
    // d_in[10] = bs: constant shift inside softmax -> cancels; unused.

    float* out = (float*)d_out;
    const int ATT_N = B_ * L_ * D_;   // 786432
    const int W_N   = B_ * L_ * L_;   // 262144

    float* out_att = nullptr;
    float* out_w   = nullptr;
    if (out_size >= ATT_N + W_N) {            // both outputs, attended first
        out_att = out;
        out_w   = out + ATT_N;
    } else if (out_size == ATT_N) {           // attended only
        out_att = out;
    } else {                                   // weights only
        out_w = out;
    }

    dim3 ggrid(D_ / 128, M_ / 64, 3);         // (6, 16, 3) = 288 CTAs
    proj_gemm_kernel<<<ggrid, 256>>>(query, key, value, Wq, bq, Wk, bk, Wv, bv);

    attn_kernel<<<B_ * (L_ / TQ), 256>>>(Ws, out_att, out_w);
}

// round 5
// speedup vs baseline: 1.3073x; 1.3073x over previous
#include <cuda_runtime.h>
#include <cuda_bf16.h>

// ---------------------------------------------------------------------------
// AdditiveAttention: B=4, LQ=LK=256, D=768
//   q = query@Wq + bq ; k = key@Wk + bk ; v = value@Wv + bv
//   scores[b,q,k] = sum_d Ws[d] * tanh(q[b,q,d] + k[b,k,d])   (+bs cancels in softmax)
//   weights = softmax_k(scores) ; attended = weights @ v
// Outputs: attended [4,256,768] then weights [4,256,256] (flattened, fp32)
// ---------------------------------------------------------------------------

#define B_ 4
#define L_ 256
#define D_ 768
#define M_ (B_ * L_)          // 1024 rows for projection GEMMs

// scratch (allocation-free rule: __device__ globals)
__device__ __align__(16) float g_qp[M_ * D_];
__device__ __align__(16) float g_kp[M_ * D_];
__device__ __align__(16) float g_vp[M_ * D_];

// ---------------------------------------------------------------------------
// Kernel 1: projection GEMM (REVERTED to round-2 config: best measured)
// Y[m,n] = sum_k X[m,k]*W[k,n] + bias[n]
// 128x128 tile, BK=8, 256 threads, 8x8 micro-tile, double-buffered smem.
// ---------------------------------------------------------------------------
__global__ __launch_bounds__(256, 1)
void proj_gemm_kernel(const float* __restrict__ Xq, const float* __restrict__ Xk,
                      const float* __restrict__ Xv,
                      const float* __restrict__ Wq, const float* __restrict__ bq,
                      const float* __restrict__ Wk, const float* __restrict__ bk,
                      const float* __restrict__ Wv, const float* __restrict__ bv)
{
    const int z = blockIdx.z;
    const float* X    = (z == 0) ? Xq : (z == 1) ? Xk : Xv;
    const float* W    = (z == 0) ? Wq : (z == 1) ? Wk : Wv;
    const float* bias = (z == 0) ? bq : (z == 1) ? bk : bv;
    float*       Y    = (z == 0) ? g_qp : (z == 1) ? g_kp : g_vp;

    __shared__ __align__(16) float As[2][8][128];
    __shared__ __align__(16) float Bs[2][8][128];

    const int tid = threadIdx.x;
    const int m0 = blockIdx.y * 128;
    const int n0 = blockIdx.x * 128;

    const int a_row = tid >> 1;
    const int a_col = (tid & 1) * 4;
    const int b_row = tid >> 5;
    const int b_col = (tid & 31) * 4;

    const float* Abase = X + (m0 + a_row) * D_ + a_col;
    const float* Bbase = W + b_row * D_ + n0 + b_col;

    const int NCHUNK = D_ / 8;   // 96

    float4 af = *(const float4*)(Abase);
    float4 bf = *(const float4*)(Bbase);

    int buf = 0;
    As[buf][a_col + 0][a_row] = af.x;
    As[buf][a_col + 1][a_row] = af.y;
    As[buf][a_col + 2][a_row] = af.z;
    As[buf][a_col + 3][a_row] = af.w;
    *(float4*)&Bs[buf][b_row][b_col] = bf;
    __syncthreads();

    const int tx = tid & 15;
    const int ty = tid >> 4;

    float acc[8][8];
    #pragma unroll
    for (int i = 0; i < 8; i++)
        #pragma unroll
        for (int j = 0; j < 8; j++) acc[i][j] = 0.f;

    for (int kt = 0; kt < NCHUNK; kt++) {
        float4 af_n, bf_n;
        if (kt + 1 < NCHUNK) {
            af_n = *(const float4*)(Abase + (kt + 1) * 8);
            bf_n = *(const float4*)(Bbase + (size_t)(kt + 1) * 8 * D_);
        }
        #pragma unroll
        for (int kk = 0; kk < 8; kk++) {
            float a_frag[8], b_frag[8];
            *(float4*)&a_frag[0] = *(const float4*)&As[buf][kk][ty * 8];
            *(float4*)&a_frag[4] = *(const float4*)&As[buf][kk][ty * 8 + 4];
            *(float4*)&b_frag[0] = *(const float4*)&Bs[buf][kk][tx * 8];
            *(float4*)&b_frag[4] = *(const float4*)&Bs[buf][kk][tx * 8 + 4];
            #pragma unroll
            for (int i = 0; i < 8; i++)
                #pragma unroll
                for (int j = 0; j < 8; j++)
                    acc[i][j] += a_frag[i] * b_frag[j];
        }
        if (kt + 1 < NCHUNK) {
            buf ^= 1;
            As[buf][a_col + 0][a_row] = af_n.x;
            As[buf][a_col + 1][a_row] = af_n.y;
            As[buf][a_col + 2][a_row] = af_n.z;
            As[buf][a_col + 3][a_row] = af_n.w;
            *(float4*)&Bs[buf][b_row][b_col] = bf_n;
            __syncthreads();
        }
    }

    float bv8[8];
    #pragma unroll
    for (int j = 0; j < 8; j++) bv8[j] = __ldg(bias + n0 + tx * 8 + j);

    #pragma unroll
    for (int i = 0; i < 8; i++) {
        float* yrow = Y + (size_t)(m0 + ty * 8 + i) * D_ + n0 + tx * 8;
        float4 o0, o1;
        o0.x = acc[i][0] + bv8[0]; o0.y = acc[i][1] + bv8[1];
        o0.z = acc[i][2] + bv8[2]; o0.w = acc[i][3] + bv8[3];
        o1.x = acc[i][4] + bv8[4]; o1.y = acc[i][5] + bv8[5];
        o1.z = acc[i][6] + bv8[6]; o1.w = acc[i][7] + bv8[7];
        *(float4*)(yrow)     = o0;
        *(float4*)(yrow + 4) = o1;
    }
}

// ---------------------------------------------------------------------------
// Kernel 2: fused scores + softmax + attended, D-SPLIT for occupancy.
// 768 threads/CTA: thread = (key = tid&255, dslice = tid>>8 of 3x256 d's).
// Chip threads 3x round-4 -> ~41 warps/SM. Partial scores reduced via smem.
// AV phase: one v-column per thread (768 = D), float4 weight loads.
// grid = 256 CTAs (TQ=4 queries each).
// ---------------------------------------------------------------------------
#define TQ 4
#define DS_ (D_ / 3)          // 256 d's per slice

__device__ __forceinline__ float tanh_fast(float x) {
    float y;
    asm("tanh.approx.f32 %0, %1;" : "=f"(y) : "f"(x));
    return y;
}

__global__ __launch_bounds__(768, 2)
void attn_kernel(const float* __restrict__ Ws,
                 float* __restrict__ out_att,   // may be null
                 float* __restrict__ out_w)     // may be null
{
    __shared__ __align__(16) float sq[TQ][D_];        // 12 KB
    __shared__ __align__(16) float sws[D_];           //  3 KB
    __shared__ __align__(16) float spart[2][TQ][L_];  //  8 KB  d-slice partials
    __shared__ __align__(16) float ssc[TQ][L_];       //  4 KB  scores -> weights
    __shared__ float smax[TQ], sinv[TQ];

    const int tid = threadIdx.x;
    const int b  = blockIdx.x >> 6;
    const int q0 = (blockIdx.x & 63) * TQ;

    const int key = tid & 255;
    const int ds  = tid >> 8;          // 0..2

    // load q tile + Ws (768 float4 total for q, one per thread)
    const float4* qbase = (const float4*)(g_qp + (size_t)(b * L_ + q0) * D_);
    ((float4*)&sq[0][0])[tid] = qbase[tid];
    if (tid < D_ / 4)
        ((float4*)sws)[tid] = ((const float4*)Ws)[tid];
    __syncthreads();

    // ---- partial scores over this thread's 256-d slice ----
    const int dbase = ds * DS_;
    const float4* kb4 = (const float4*)(g_kp + ((size_t)b * L_ + key) * D_ + dbase);
    float acc[TQ];
    #pragma unroll
    for (int q = 0; q < TQ; q++) acc[q] = 0.f;

    float4 c0 = kb4[0], c1 = kb4[1];
    #pragma unroll 1
    for (int ch = 0; ch < DS_ / 8; ch++) {      // 32 chunks of 8
        float4 p0, p1;
        if (ch + 1 < DS_ / 8) {
            p0 = kb4[(ch + 1) * 2];
            p1 = kb4[(ch + 1) * 2 + 1];
        }
        const int d0 = dbase + ch * 8;
        const float4 w0 = *(const float4*)&sws[d0];
        const float4 w1 = *(const float4*)&sws[d0 + 4];
        #pragma unroll
        for (int q = 0; q < TQ; q++) {
            const float4 a0 = *(const float4*)&sq[q][d0];
            const float4 a1 = *(const float4*)&sq[q][d0 + 4];
            float s;
            s  = w0.x * tanh_fast(a0.x + c0.x);
            s += w0.y * tanh_fast(a0.y + c0.y);
            s += w0.z * tanh_fast(a0.z + c0.z);
            s += w0.w * tanh_fast(a0.w + c0.w);
            s += w1.x * tanh_fast(a1.x + c1.x);
            s += w1.y * tanh_fast(a1.y + c1.y);
            s += w1.z * tanh_fast(a1.z + c1.z);
            s += w1.w * tanh_fast(a1.w + c1.w);
            acc[q] += s;
        }
        c0 = p0; c1 = p1;
    }

    if (ds > 0) {
        #pragma unroll
        for (int q = 0; q < TQ; q++) spart[ds - 1][q][key] = acc[q];
    }
    __syncthreads();

    // ---- combine slices + softmax (first 256 threads own keys) ----
    if (ds == 0) {
        #pragma unroll
        for (int q = 0; q < TQ; q++)
            ssc[q][key] = acc[q] + spart[0][q][key] + spart[1][q][key];
    }
    __syncthreads();

    const int w = tid >> 5, lane = tid & 31;
    if (w < TQ) {
        float m = -1e30f;
        #pragma unroll
        for (int j = 0; j < 8; j++) m = fmaxf(m, ssc[w][lane + j * 32]);
        #pragma unroll
        for (int o = 16; o > 0; o >>= 1) m = fmaxf(m, __shfl_xor_sync(0xffffffffu, m, o));
        float s = 0.f;
        #pragma unroll
        for (int j = 0; j < 8; j++) s += __expf(ssc[w][lane + j * 32] - m);
        #pragma unroll
        for (int o = 16; o > 0; o >>= 1) s += __shfl_xor_sync(0xffffffffu, s, o);
        if (lane == 0) { smax[w] = m; sinv[w] = 1.0f / s; }
    }
    __syncthreads();

    if (ds == 0) {
        #pragma unroll
        for (int q = 0; q < TQ; q++) {
            const float wt = __expf(ssc[q][key] - smax[q]) * sinv[q];
            ssc[q][key] = wt;
            if (out_w)
                out_w[((size_t)(b * L_ + q0 + q)) * L_ + key] = wt;
        }
    }
    __syncthreads();

    // ---- attended: thread owns column tid (768 = D); float4 weight loads ----
    if (out_att) {
        float a[TQ];
        #pragma unroll
        for (int q = 0; q < TQ; q++) a[q] = 0.f;
        const float* vcol = g_vp + (size_t)b * L_ * D_ + tid;
        #pragma unroll 1
        for (int kk = 0; kk < L_; kk += 4) {
            const float v0 = vcol[(size_t)(kk + 0) * D_];
            const float v1 = vcol[(size_t)(kk + 1) * D_];
            const float v2 = vcol[(size_t)(kk + 2) * D_];
            const float v3 = vcol[(size_t)(kk + 3) * D_];
            #pragma unroll
            for (int q = 0; q < TQ; q++) {
                const float4 wq = *(const float4*)&ssc[q][kk];
                a[q] += wq.x * v0 + wq.y * v1 + wq.z * v2 + wq.w * v3;
            }
        }
        #pragma unroll
        for (int q = 0; q < TQ; q++)
            out_att[((size_t)(b * L_ + q0 + q)) * D_ + tid] = a[q];
    }
}

// ---------------------------------------------------------------------------
extern "C" void kernel_launch(void* const* d_in, const int* in_sizes, int n_in,
                              void* d_out, int out_size)
{
    const float* query = (const float*)d_in[0];
    const float* key   = (const float*)d_in[1];
    const float* value = (const float*)d_in[2];
    const float* Wq    = (const float*)d_in[3];
    const float* bq    = (const float*)d_in[4];
    const float* Wk    = (const float*)d_in[5];
    const float* bk    = (const float*)d_in[6];
    const float* Wv    = (const float*)d_in[7];
    const float* bv    = (const float*)d_in[8];
    const float* Ws    = (const float*)d_in[9];
    // d_in[10] = bs: constant shift inside softmax -> cancels; unused.

    float* out = (float*)d_out;
    const int ATT_N = B_ * L_ * D_;   // 786432
    const int W_N   = B_ * L_ * L_;   // 262144

    float* out_att = nullptr;
    float* out_w   = nullptr;
    if (out_size >= ATT_N + W_N) {            // both outputs, attended first
        out_att = out;
        out_w   = out + ATT_N;
    } else if (out_size == ATT_N) {           // attended only
        out_att = out;
    } else {                                   // weights only
        out_w = out;
    }

    dim3 ggrid(D_ / 128, M_ / 128, 3);        // (6, 8, 3) = 144 CTAs
    proj_gemm_kernel<<<ggrid, 256>>>(query, key, value, Wq, bq, Wk, bk, Wv, bv);

    attn_kernel<<<B_ * (L_ / TQ), 768>>>(Ws, out_att, out_w);
}